// round 2
// baseline (speedup 1.0000x reference)
#include <cuda_runtime.h>
#include <math_constants.h>

#define B_SZ  2048
#define FEAT  840
#define HID   256
#define LAT   128
#define NQ    12
#define NEMB  512
#define KTOT  (HID*3)   /* 768 */

#define TC    64
#define NCH   14        /* ceil(840/64) */
#define CG    64        /* channels per group */
#define NG    (HID/CG)  /* 4 */
#define RS    68        /* r1s row stride (floats), >= 66+2, mult of 4 */

// Static device scratch (no runtime allocation)
__device__ __align__(16) float g_w2t[KTOT*LAT];   // [(k*256+c)][l]
__device__ float g_cnorm[NQ*NEMB];
__device__ __align__(16) float g_z[B_SZ*LAT];

// ---------------------------------------------------------------------------
// Prep: w2 -> K-major transpose; per-code squared norms.
// ---------------------------------------------------------------------------
__global__ void prep_kernel(const float* __restrict__ w2,
                            const float* __restrict__ cb)
{
    int i = blockIdx.x * blockDim.x + threadIdx.x;
    if (i < KTOT*LAT) {
        int l  = i & 127;
        int kk = i >> 7;          // 0..767
        int c  = kk & 255;
        int k  = kk >> 8;         // 0..2
        g_w2t[i] = w2[l*KTOT + c*3 + k];
    } else {
        int j = i - KTOT*LAT;
        if (j < NQ*NEMB) {
            const float4* row = (const float4*)(cb + (size_t)j*LAT);
            float s = 0.f;
            #pragma unroll
            for (int m = 0; m < LAT/4; m++) {
                float4 v = row[m];
                s = __fmaf_rn(v.x, v.x, s);
                s = __fmaf_rn(v.y, v.y, s);
                s = __fmaf_rn(v.z, v.z, s);
                s = __fmaf_rn(v.w, v.w, s);
            }
            g_cnorm[j] = s;
        }
    }
}

// ---------------------------------------------------------------------------
// Encoder: fused conv1 -> relu -> conv2 -> relu -> mean(t).  One CTA per row.
// Dyn smem layout (floats):
//   xs  [844]            x row, xs[0]=xs[841]=0 pad
//   w1s [768], b1s[256]
//   r1s [CG*RS]          h1 for current 64-channel group, tt in [0,66)
//   At  [CG*128]         w2t tile for (group, tap)
// ---------------------------------------------------------------------------
#define XS_OFF   0
#define W1_OFF   844
#define B1_OFF   (844+768)
#define R1_OFF   (844+768+256)          /* 1868, mult of 4 */
#define AT_OFF   (R1_OFF + CG*RS)       /* 1868+4352=6220, mult of 4 */
#define SMEM_FLOATS (AT_OFF + CG*LAT)   /* 6220+8192=14412 -> 57648 B */

__global__ void __launch_bounds__(256, 3)
encoder_kernel(const float* __restrict__ x,  const float* __restrict__ w1,
               const float* __restrict__ b1, const float* __restrict__ b2)
{
    extern __shared__ float sm[];
    float* xs  = sm + XS_OFF;
    float* w1s = sm + W1_OFF;
    float* b1s = sm + B1_OFF;
    float* r1s = sm + R1_OFF;
    float* At  = sm + AT_OFF;

    const int b    = blockIdx.x;
    const int tid  = threadIdx.x;
    const int lane = tid & 31;
    const int w8   = tid >> 5;    // warp id 0..7
    const int tx   = tid & 7;     // 8 threads x 8 t = 64 t
    const int ty   = tid >> 3;    // 32 threads x 4 l = 128 l

    for (int i = tid; i < FEAT; i += 256) xs[i + 1] = x[(size_t)b*FEAT + i];
    for (int i = tid; i < HID*3; i += 256) w1s[i] = w1[i];
    if (tid < HID) b1s[tid] = b1[tid];
    if (tid == 0) { xs[0] = 0.f; xs[FEAT + 1] = 0.f; xs[FEAT + 2] = 0.f; }

    float bl[4];
    #pragma unroll
    for (int j = 0; j < 4; j++) bl[j] = b2[ty*4 + j];

    double zp[4] = {0.0, 0.0, 0.0, 0.0};   // exact t-sum (mean) accumulator

    __syncthreads();

    for (int ch = 0; ch < NCH; ch++) {
        const int t0 = ch * TC;

        float acc[4][8];
        #pragma unroll
        for (int j = 0; j < 4; j++)
            #pragma unroll
            for (int i = 0; i < 8; i++) acc[j][i] = 0.f;

        for (int g = 0; g < NG; g++) {
            __syncthreads();  // r1s/At free of prior readers

            // conv1 + bias + relu for channels [g*64, g*64+64), tt in [0,66)
            #pragma unroll
            for (int c8 = 0; c8 < 8; c8++) {
                const int cc = w8*8 + c8;
                const int c  = g*CG + cc;
                const float wa = w1s[c*3+0], wb = w1s[c*3+1], wc = w1s[c*3+2];
                const float bb1 = b1s[c];
                #pragma unroll
                for (int s = 0; s < 3; s++) {
                    int tt = lane + 32*s;
                    if (tt < 66) {
                        int t = t0 - 1 + tt;
                        float v = 0.f;
                        if ((unsigned)t < (unsigned)FEAT) {
                            v = __fmul_rn(wa, xs[t]);          // x[t-1]
                            v = __fmaf_rn(wb, xs[t+1], v);     // x[t]
                            v = __fmaf_rn(wc, xs[t+2], v);     // x[t+1]
                            v = fmaxf(__fadd_rn(v, bb1), 0.f);
                        }
                        r1s[cc*RS + tt] = v;
                    }
                }
            }

            #pragma unroll
            for (int k = 0; k < 3; k++) {
                __syncthreads();   // prior GEMM done with At (and r1s ready at k=0)
                {   // stage 64x128 w2t tile (contiguous block)
                    const float4* src = (const float4*)(g_w2t + (size_t)(k*HID + g*CG)*LAT);
                    float4* dst = (float4*)At;
                    #pragma unroll
                    for (int r = 0; r < 8; r++) dst[tid + r*256] = src[tid + r*256];
                }
                __syncthreads();

                #pragma unroll 4
                for (int kk = 0; kk < CG; kk++) {
                    const float4 a = *(const float4*)(At + kk*LAT + ty*4);
                    const float* br = r1s + kk*RS + tx*8;
                    float4 b0 = *(const float4*)(br);
                    float4 b1v = *(const float4*)(br + 4);
                    float4 b2v = *(const float4*)(br + 8);
                    float bb[12] = {b0.x,b0.y,b0.z,b0.w,
                                    b1v.x,b1v.y,b1v.z,b1v.w,
                                    b2v.x,b2v.y,b2v.z,b2v.w};
                    #pragma unroll
                    for (int i = 0; i < 8; i++) {
                        float bv = bb[k + i];   // k compile-time (unrolled)
                        acc[0][i] = __fmaf_rn(a.x, bv, acc[0][i]);
                        acc[1][i] = __fmaf_rn(a.y, bv, acc[1][i]);
                        acc[2][i] = __fmaf_rn(a.z, bv, acc[2][i]);
                        acc[3][i] = __fmaf_rn(a.w, bv, acc[3][i]);
                    }
                }
            }
        }

        // relu(conv2+b2), masked accumulation toward the mean
        #pragma unroll
        for (int i = 0; i < 8; i++) {
            if (t0 + tx*8 + i < FEAT) {
                #pragma unroll
                for (int j = 0; j < 4; j++)
                    zp[j] += (double)fmaxf(__fadd_rn(acc[j][i], bl[j]), 0.f);
            }
        }
    }

    // reduce the 8 tx-lanes sharing each l (lane bits 0..2), then mean
    #pragma unroll
    for (int j = 0; j < 4; j++) {
        double v = zp[j];
        v += __shfl_xor_sync(0xffffffffu, v, 1);
        v += __shfl_xor_sync(0xffffffffu, v, 2);
        v += __shfl_xor_sync(0xffffffffu, v, 4);
        if (tx == 0)
            g_z[(size_t)b*LAT + ty*4 + j] = __fdiv_rn((float)v, (float)FEAT);
    }
}

// ---------------------------------------------------------------------------
// RVQ: one warp per row, 8 rows/CTA. d = fl(fl(||r||^2 - 2 r.c) + ||c||^2)
// exactly mirrors the reference's ((A - 2B) + C) fp32 rounding structure so
// grid-level ties resolve identically (first index wins).
// ---------------------------------------------------------------------------
__global__ void __launch_bounds__(256)
rvq_kernel(const float* __restrict__ cb,
           float* __restrict__ out_zq, float* __restrict__ out_idx,
           int write_zq, int write_idx)
{
    __shared__ __align__(16) float res[8][LAT];
    __shared__ int sidx[8][NQ];

    const int tid  = threadIdx.x;
    const int w    = tid >> 5;
    const int lane = tid & 31;
    const int b    = blockIdx.x * 8 + w;

    float qs[4] = {0.f, 0.f, 0.f, 0.f};   // fp32 sum of chosen codes (matches qs.sum)
    #pragma unroll
    for (int m = 0; m < 4; m++)
        res[w][lane + 32*m] = g_z[(size_t)b*LAT + lane + 32*m];
    __syncwarp();

    for (int q = 0; q < NQ; q++) {
        const float* cbq = cb + (size_t)q*NEMB*LAT;
        const float* cnq = g_cnorm + q*NEMB;

        // A = ||r||^2 in fp32 (lane partials + warp tree; shift-invariant)
        float A;
        {
            float s = 0.f;
            #pragma unroll
            for (int m = 0; m < 4; m++) {
                float rv = res[w][lane + 32*m];
                s = __fmaf_rn(rv, rv, s);
            }
            #pragma unroll
            for (int off = 16; off > 0; off >>= 1)
                s = __fadd_rn(s, __shfl_xor_sync(0xffffffffu, s, off));
            A = s;
        }

        float best = CUDART_INF_F;
        int   bj   = 0x7fffffff;
        #pragma unroll 1
        for (int jj = 0; jj < NEMB/32; jj++) {
            const int j = (lane << 4) + jj;
            const float4* crow = (const float4*)(cbq + (size_t)j*LAT);
            const float4* rrow = (const float4*)(res[w]);
            float dot = 0.f;
            #pragma unroll
            for (int m = 0; m < LAT/4; m++) {
                float4 cv = crow[m];
                float4 rv = rrow[m];
                dot = __fmaf_rn(cv.x, rv.x, dot);
                dot = __fmaf_rn(cv.y, rv.y, dot);
                dot = __fmaf_rn(cv.z, rv.z, dot);
                dot = __fmaf_rn(cv.w, rv.w, dot);
            }
            float t1 = __fmaf_rn(-2.f, dot, A);   // fl(A - 2*dot)
            float d  = __fadd_rn(t1, cnq[j]);     // fl(.. + ||c||^2)
            if (d < best || (d == best && j < bj)) { best = d; bj = j; }
        }
        #pragma unroll
        for (int off = 16; off > 0; off >>= 1) {
            float ob = __shfl_xor_sync(0xffffffffu, best, off);
            int   oj = __shfl_xor_sync(0xffffffffu, bj,   off);
            if (ob < best || (ob == best && oj < bj)) { best = ob; bj = oj; }
        }
        if (lane == 0) sidx[w][q] = bj;

        #pragma unroll
        for (int m = 0; m < 4; m++) {
            int d = lane + 32*m;
            float c = cbq[(size_t)bj*LAT + d];
            res[w][d] = __fadd_rn(res[w][d], -c);   // residual -= q (fp32)
            qs[m] = __fadd_rn(qs[m], c);            // zq accumulation (fp32)
        }
        __syncwarp();
    }

    if (write_zq) {
        #pragma unroll
        for (int m = 0; m < 4; m++)
            out_zq[(size_t)b*LAT + lane + 32*m] = qs[m];
    }
    if (write_idx && lane < NQ)
        out_idx[(size_t)b*NQ + lane] = (float)sidx[w][lane];
}

// ---------------------------------------------------------------------------
extern "C" void kernel_launch(void* const* d_in, const int* in_sizes, int n_in,
                              void* d_out, int out_size)
{
    const float* x  = (const float*)d_in[0];
    const float* w1 = (const float*)d_in[1];
    const float* b1 = (const float*)d_in[2];
    const float* w2 = (const float*)d_in[3];
    const float* b2 = (const float*)d_in[4];
    const float* cb = (const float*)d_in[5];

    static int attr_done = 0;
    if (!attr_done) {
        cudaFuncSetAttribute(encoder_kernel,
                             cudaFuncAttributeMaxDynamicSharedMemorySize,
                             SMEM_FLOATS * (int)sizeof(float));
        attr_done = 1;
    }

    const int total = (KTOT*LAT) + (NQ*NEMB);
    prep_kernel<<<(total + 255)/256, 256>>>(w2, cb);
    encoder_kernel<<<B_SZ, 256, SMEM_FLOATS * sizeof(float)>>>(x, w1, b1, b2);

    // Output: flattened concat fp32: zq (B*128) then idx (B*12). Guard by size.
    float* out_zq  = (float*)d_out;
    float* out_idx = (float*)d_out + (size_t)B_SZ*LAT;
    int write_zq = 1, write_idx = 1;
    if (out_size >= B_SZ*(LAT + NQ)) {
        // both
    } else if (out_size >= B_SZ*LAT) {
        write_idx = 0;
    } else {
        write_zq = 0;
        out_idx  = (float*)d_out;
    }
    rvq_kernel<<<B_SZ/8, 256>>>(cb, out_zq, out_idx, write_zq, write_idx);
}

// round 7
// speedup vs baseline: 1.2460x; 1.2460x over previous
#include <cuda_runtime.h>
#include <math_constants.h>
#include <cstdint>

#define B_SZ  2048
#define FEAT  840
#define HID   256
#define LAT   128
#define NQ    12
#define NEMB  512
#define KTOT  (HID*3)   /* 768 */

#define TC    64
#define NCH   14        /* ceil(840/64) */
#define CG    64        /* channels per group */
#define NG    4
#define RSP   68        /* r1s2 row stride in ull (>= 66), keeps 16B align */

typedef unsigned long long ull;

// Static device scratch
__device__ __align__(16) float g_w2t[KTOT*LAT];   // [(k*256+c)][l]
__device__ float g_cnorm[NQ*NEMB];
__device__ __align__(16) float g_z[B_SZ*LAT];

// packed fp32x2 FMA: per-lane .rn rounding == scalar __fmaf_rn, bit-exact per lane
__device__ __forceinline__ ull ffma2(ull a, ull b, ull c){
    ull d;
    asm("fma.rn.f32x2 %0, %1, %2, %3;" : "=l"(d) : "l"(a), "l"(b), "l"(c));
    return d;
}
__device__ __forceinline__ float2 unpack2(ull v){
    float2 f; asm("mov.b64 {%0,%1}, %2;" : "=f"(f.x), "=f"(f.y) : "l"(v));
    return f;
}
__device__ __forceinline__ ull splat2(float v){
    ull d; asm("mov.b64 %0, {%1,%1};" : "=l"(d) : "f"(v));
    return d;
}

// ---------------------------------------------------------------------------
// Prep: w2 -> K-major transpose; per-code squared norms.  (R2 verbatim)
// ---------------------------------------------------------------------------
__global__ void prep_kernel(const float* __restrict__ w2,
                            const float* __restrict__ cb)
{
    int i = blockIdx.x * blockDim.x + threadIdx.x;
    if (i < KTOT*LAT) {
        int l  = i & 127;
        int kk = i >> 7;
        int c  = kk & 255;
        int k  = kk >> 8;
        g_w2t[i] = w2[l*KTOT + c*3 + k];
    } else {
        int j = i - KTOT*LAT;
        if (j < NQ*NEMB) {
            const float4* row = (const float4*)(cb + (size_t)j*LAT);
            float s = 0.f;
            #pragma unroll
            for (int m = 0; m < LAT/4; m++) {
                float4 v = row[m];
                s = __fmaf_rn(v.x, v.x, s);
                s = __fmaf_rn(v.y, v.y, s);
                s = __fmaf_rn(v.z, v.z, s);
                s = __fmaf_rn(v.w, v.w, s);
            }
            g_cnorm[j] = s;
        }
    }
}

// ---------------------------------------------------------------------------
// Encoder: fused conv1 -> relu -> conv2 -> relu -> mean(t).  One CTA per row.
// Per-element conv2 FMA chain identical to the proven R2 kernel:
//   for g in 0..3: for k in 0..2: for kk in 0..63: acc = fma(w2t, r1, acc)
// computed 2 elements (adjacent l) per FFMA2 instruction.
// smem floats: xs[844] | w1s[768] | b1s[256] | r1s2[64*RSP ull]
// ---------------------------------------------------------------------------
#define XS_O   0
#define W1_O   844
#define B1_O   (844+768)
#define R1_O   (844+768+256)               /* 1868 floats, 16B aligned */
#define ENC_SMEM_FLOATS (R1_O + CG*RSP*2)  /* 1868 + 8704 = 10572 */
#define ENC_SMEM_BYTES  (ENC_SMEM_FLOATS*4)

__global__ void __launch_bounds__(256, 2)
encoder_kernel(const float* __restrict__ x,  const float* __restrict__ w1,
               const float* __restrict__ b1, const float* __restrict__ b2)
{
    extern __shared__ float sm[];
    float* xs  = sm + XS_O;
    float* w1s = sm + W1_O;
    float* b1s = sm + B1_O;
    ull*   r1s2 = (ull*)(sm + R1_O);

    const int b    = blockIdx.x;
    const int tid  = threadIdx.x;
    const int lane = tid & 31;
    const int w8   = tid >> 5;          // warp id 0..7 == t-subwindow
    const int l0   = lane * 4;          // 4 l per thread (2 FFMA2 pairs)

    for (int i = tid; i < FEAT; i += 256) xs[i + 1] = x[(size_t)b*FEAT + i];
    for (int i = tid; i < HID*3; i += 256) w1s[i] = w1[i];
    if (tid < HID) b1s[tid] = b1[tid];
    if (tid == 0) { xs[0] = 0.f; xs[FEAT + 1] = 0.f; xs[FEAT + 2] = 0.f; }

    float bl[4];
    #pragma unroll
    for (int j = 0; j < 4; j++) bl[j] = b2[l0 + j];

    double zp[4] = {0.0, 0.0, 0.0, 0.0};

    __syncthreads();

    for (int ch = 0; ch < NCH; ch++) {
        const int t0 = ch * TC;

        ull acc[2][8];
        #pragma unroll
        for (int p = 0; p < 2; p++)
            #pragma unroll
            for (int i = 0; i < 8; i++) acc[p][i] = 0ull;

        for (int g = 0; g < NG; g++) {
            __syncthreads();  // r1s2 free of readers

            // conv1 + bias + relu for channels [g*64, g*64+64), tt in [0,66)
            // formula and per-element op order identical to R2
            #pragma unroll
            for (int c8 = 0; c8 < 8; c8++) {
                const int cc = w8*8 + c8;
                const int c  = g*CG + cc;
                const float wa = w1s[c*3+0], wb = w1s[c*3+1], wc = w1s[c*3+2];
                const float bb1 = b1s[c];
                #pragma unroll
                for (int s = 0; s < 3; s++) {
                    int tt = lane + 32*s;
                    if (tt < 66) {
                        int t = t0 - 1 + tt;
                        float v = 0.f;
                        if ((unsigned)t < (unsigned)FEAT) {
                            v = __fmul_rn(wa, xs[t]);
                            v = __fmaf_rn(wb, xs[t+1], v);
                            v = __fmaf_rn(wc, xs[t+2], v);
                            v = fmaxf(__fadd_rn(v, bb1), 0.f);
                        }
                        r1s2[cc*RSP + tt] = splat2(v);   // pre-splatted {v,v}
                    }
                }
            }
            __syncthreads();

            #pragma unroll
            for (int k = 0; k < 3; k++) {
                const ulonglong2* wrow =
                    (const ulonglong2*)(g_w2t + (size_t)(k*HID + g*CG)*LAT);
                #pragma unroll 4
                for (int kk = 0; kk < CG; kk++) {
                    // a: 4 w2 values for this (channel,tap) at l0..l0+4  (L2-resident)
                    ulonglong2 a2 = __ldg(wrow + kk*32 + lane);
                    // b: 10 splatted r1 pairs covering window [w8*8+k, +8)
                    const ulonglong2* brow = (const ulonglong2*)(r1s2 + kk*RSP) + w8*4;
                    ull bw[10];
                    #pragma unroll
                    for (int j = 0; j < 5; j++) {
                        ulonglong2 bb = brow[j];       // broadcast LDS.128
                        bw[2*j]   = bb.x;
                        bw[2*j+1] = bb.y;
                    }
                    #pragma unroll
                    for (int i = 0; i < 8; i++) {
                        ull bs = bw[k + i];
                        acc[0][i] = ffma2(a2.x, bs, acc[0][i]);
                        acc[1][i] = ffma2(a2.y, bs, acc[1][i]);
                    }
                }
            }
        }

        // relu(conv2 + b2), masked fp64 accumulation toward the mean
        #pragma unroll
        for (int i = 0; i < 8; i++) {
            if (t0 + w8*8 + i < FEAT) {
                #pragma unroll
                for (int p = 0; p < 2; p++) {
                    float2 f = unpack2(acc[p][i]);
                    zp[2*p+0] += (double)fmaxf(__fadd_rn(f.x, bl[2*p+0]), 0.f);
                    zp[2*p+1] += (double)fmaxf(__fadd_rn(f.y, bl[2*p+1]), 0.f);
                }
            }
        }
    }

    // cross-warp fp64 reduce (fixed order), then mean
    __syncthreads();
    double* dp = (double*)(sm + R1_O);   // overlaps r1s2 (dead)
    #pragma unroll
    for (int j = 0; j < 4; j++) dp[w8*128 + l0 + j] = zp[j];
    __syncthreads();
    if (tid < LAT) {
        double v = dp[tid];
        #pragma unroll
        for (int w = 1; w < 8; w++) v += dp[w*128 + tid];
        g_z[(size_t)b*LAT + tid] = __fdiv_rn((float)v, (float)FEAT);
    }
}

// ---------------------------------------------------------------------------
// RVQ (verbatim from the passing R2 kernel)
// ---------------------------------------------------------------------------
__global__ void __launch_bounds__(256)
rvq_kernel(const float* __restrict__ cb,
           float* __restrict__ out_zq, float* __restrict__ out_idx,
           int write_zq, int write_idx)
{
    __shared__ __align__(16) float res[8][LAT];
    __shared__ int sidx[8][NQ];

    const int tid  = threadIdx.x;
    const int w    = tid >> 5;
    const int lane = tid & 31;
    const int b    = blockIdx.x * 8 + w;

    float qs[4] = {0.f, 0.f, 0.f, 0.f};
    #pragma unroll
    for (int m = 0; m < 4; m++)
        res[w][lane + 32*m] = g_z[(size_t)b*LAT + lane + 32*m];
    __syncwarp();

    for (int q = 0; q < NQ; q++) {
        const float* cbq = cb + (size_t)q*NEMB*LAT;
        const float* cnq = g_cnorm + q*NEMB;

        float A;
        {
            float sA = 0.f;
            #pragma unroll
            for (int m = 0; m < 4; m++) {
                float rv = res[w][lane + 32*m];
                sA = __fmaf_rn(rv, rv, sA);
            }
            #pragma unroll
            for (int off = 16; off > 0; off >>= 1)
                sA = __fadd_rn(sA, __shfl_xor_sync(0xffffffffu, sA, off));
            A = sA;
        }

        float best = CUDART_INF_F;
        int   bj   = 0x7fffffff;
        #pragma unroll 1
        for (int jj = 0; jj < NEMB/32; jj++) {
            const int j = (lane << 4) + jj;
            const float4* crow = (const float4*)(cbq + (size_t)j*LAT);
            const float4* rrow = (const float4*)(res[w]);
            float dot = 0.f;
            #pragma unroll
            for (int m = 0; m < LAT/4; m++) {
                float4 cv = crow[m];
                float4 rv = rrow[m];
                dot = __fmaf_rn(cv.x, rv.x, dot);
                dot = __fmaf_rn(cv.y, rv.y, dot);
                dot = __fmaf_rn(cv.z, rv.z, dot);
                dot = __fmaf_rn(cv.w, rv.w, dot);
            }
            float t1 = __fmaf_rn(-2.f, dot, A);
            float d  = __fadd_rn(t1, cnq[j]);
            if (d < best || (d == best && j < bj)) { best = d; bj = j; }
        }
        #pragma unroll
        for (int off = 16; off > 0; off >>= 1) {
            float ob = __shfl_xor_sync(0xffffffffu, best, off);
            int   oj = __shfl_xor_sync(0xffffffffu, bj,   off);
            if (ob < best || (ob == best && oj < bj)) { best = ob; bj = oj; }
        }
        if (lane == 0) sidx[w][q] = bj;

        #pragma unroll
        for (int m = 0; m < 4; m++) {
            int d = lane + 32*m;
            float c = cbq[(size_t)bj*LAT + d];
            res[w][d] = __fadd_rn(res[w][d], -c);
            qs[m] = __fadd_rn(qs[m], c);
        }
        __syncwarp();
    }

    if (write_zq) {
        #pragma unroll
        for (int m = 0; m < 4; m++)
            out_zq[(size_t)b*LAT + lane + 32*m] = qs[m];
    }
    if (write_idx && lane < NQ)
        out_idx[(size_t)b*NQ + lane] = (float)sidx[w][lane];
}

// ---------------------------------------------------------------------------
extern "C" void kernel_launch(void* const* d_in, const int* in_sizes, int n_in,
                              void* d_out, int out_size)
{
    const float* x  = (const float*)d_in[0];
    const float* w1 = (const float*)d_in[1];
    const float* b1 = (const float*)d_in[2];
    const float* w2 = (const float*)d_in[3];
    const float* b2 = (const float*)d_in[4];
    const float* cb = (const float*)d_in[5];

    cudaFuncSetAttribute(encoder_kernel,
                         cudaFuncAttributeMaxDynamicSharedMemorySize,
                         ENC_SMEM_BYTES);

    const int total = (KTOT*LAT) + (NQ*NEMB);
    prep_kernel<<<(total + 255)/256, 256>>>(w2, cb);
    encoder_kernel<<<B_SZ, 256, ENC_SMEM_BYTES>>>(x, w1, b1, b2);

    float* out_zq  = (float*)d_out;
    float* out_idx = (float*)d_out + (size_t)B_SZ*LAT;
    int write_zq = 1, write_idx = 1;
    if (out_size >= B_SZ*(LAT + NQ)) {
        // both
    } else if (out_size >= B_SZ*LAT) {
        write_idx = 0;
    } else {
        write_zq = 0;
        out_idx  = (float*)d_out;
    }
    rvq_kernel<<<B_SZ/8, 256>>>(cb, out_zq, out_idx, write_zq, write_idx);
}

// round 8
// speedup vs baseline: 1.2906x; 1.0358x over previous
#include <cuda_runtime.h>
#include <math_constants.h>
#include <cstdint>

#define B_SZ  2048
#define FEAT  840
#define HID   256
#define LAT   128
#define NQ    12
#define NEMB  512
#define KTOT  (HID*3)   /* 768 */

#define TC    128
#define NCH   7         /* 7*128 = 896 >= 840 */
#define CG    64        /* channels per group */
#define NG    4
#define RSP   132       /* r1s2 row stride in ull (>= 130), even for 16B align */

typedef unsigned long long ull;

// Static device scratch
__device__ __align__(16) float g_w2t[KTOT*LAT];   // [(k*256+c)][l]
__device__ float g_cnorm[NQ*NEMB];
__device__ __align__(16) float g_z[B_SZ*LAT];

// packed fp32x2 FMA: per-lane .rn rounding == scalar __fmaf_rn, bit-exact per lane
__device__ __forceinline__ ull ffma2(ull a, ull b, ull c){
    ull d;
    asm("fma.rn.f32x2 %0, %1, %2, %3;" : "=l"(d) : "l"(a), "l"(b), "l"(c));
    return d;
}
__device__ __forceinline__ float2 unpack2(ull v){
    float2 f; asm("mov.b64 {%0,%1}, %2;" : "=f"(f.x), "=f"(f.y) : "l"(v));
    return f;
}
__device__ __forceinline__ ull splat2(float v){
    ull d; asm("mov.b64 %0, {%1,%1};" : "=l"(d) : "f"(v));
    return d;
}

// ---------------------------------------------------------------------------
// Prep: w2 -> K-major transpose; per-code squared norms.  (verbatim)
// ---------------------------------------------------------------------------
__global__ void prep_kernel(const float* __restrict__ w2,
                            const float* __restrict__ cb)
{
    int i = blockIdx.x * blockDim.x + threadIdx.x;
    if (i < KTOT*LAT) {
        int l  = i & 127;
        int kk = i >> 7;
        int c  = kk & 255;
        int k  = kk >> 8;
        g_w2t[i] = w2[l*KTOT + c*3 + k];
    } else {
        int j = i - KTOT*LAT;
        if (j < NQ*NEMB) {
            const float4* row = (const float4*)(cb + (size_t)j*LAT);
            float s = 0.f;
            #pragma unroll
            for (int m = 0; m < LAT/4; m++) {
                float4 v = row[m];
                s = __fmaf_rn(v.x, v.x, s);
                s = __fmaf_rn(v.y, v.y, s);
                s = __fmaf_rn(v.z, v.z, s);
                s = __fmaf_rn(v.w, v.w, s);
            }
            g_cnorm[j] = s;
        }
    }
}

// ---------------------------------------------------------------------------
// Encoder: fused conv1 -> relu -> conv2 -> relu -> mean(t).  One CTA per row.
// Per-element conv2 fp32 chain identical to R2/R7:
//   for g: for k: for kk: acc = fma(w2t[k][g*64+kk][l], r1[g*64+kk][t-1+k], acc)
// computed 2 adjacent-l elements per FFMA2.
// smem floats: xs[844] | w1s[768] | b1s[256] | r1s2[64*RSP ull] | w2 tile[8192]
// ---------------------------------------------------------------------------
#define XS_O   0
#define W1_O   844
#define B1_O   (844+768)
#define R1_O   (844+768+256)               /* 1868 floats, 16B aligned */
#define W2T_O  (R1_O + CG*RSP*2)           /* 1868 + 16896 = 18764 */
#define ENC_SMEM_FLOATS (W2T_O + CG*LAT)   /* 18764 + 8192 = 26956 */
#define ENC_SMEM_BYTES  (ENC_SMEM_FLOATS*4) /* 107824 B */

__global__ void __launch_bounds__(256, 2)
encoder_kernel(const float* __restrict__ x,  const float* __restrict__ w1,
               const float* __restrict__ b1, const float* __restrict__ b2)
{
    extern __shared__ float sm[];
    float* xs  = sm + XS_O;
    float* w1s = sm + W1_O;
    float* b1s = sm + B1_O;
    ull*   r1s2 = (ull*)(sm + R1_O);
    const ulonglong2* wt = (const ulonglong2*)(sm + W2T_O);

    const int b    = blockIdx.x;
    const int tid  = threadIdx.x;
    const int lane = tid & 31;
    const int w8   = tid >> 5;          // warp id 0..7 == 16-t subwindow
    const int l0   = lane * 4;          // 4 l per thread (2 FFMA2 pairs)

    // gen mapping: 4 threads per channel
    const int gcc = tid >> 2;           // channel-in-group 0..63
    const int gsub = tid & 3;

    for (int i = tid; i < FEAT; i += 256) xs[i + 1] = x[(size_t)b*FEAT + i];
    for (int i = tid; i < HID*3; i += 256) w1s[i] = w1[i];
    if (tid < HID) b1s[tid] = b1[tid];
    if (tid == 0) { xs[0] = 0.f; xs[FEAT + 1] = 0.f; xs[FEAT + 2] = 0.f; }

    float bl[4];
    #pragma unroll
    for (int j = 0; j < 4; j++) bl[j] = b2[l0 + j];

    double zp[4] = {0.0, 0.0, 0.0, 0.0};

    __syncthreads();

    for (int ch = 0; ch < NCH; ch++) {
        const int t0 = ch * TC;

        ull acc[2][16];
        #pragma unroll
        for (int p = 0; p < 2; p++)
            #pragma unroll
            for (int i = 0; i < 16; i++) acc[p][i] = 0ull;

        for (int g = 0; g < NG; g++) {
            __syncthreads();  // previous readers done with r1s2

            // conv1 + bias + relu for channels [g*64, g*64+64), tt in [0,130)
            // (same per-element formula as the proven kernel)
            {
                const int c  = g*CG + gcc;
                const float wa = w1s[c*3+0], wb = w1s[c*3+1], wc = w1s[c*3+2];
                const float bb1 = b1s[c];
                #pragma unroll
                for (int s = 0; s < 33; s++) {
                    int tt = gsub + 4*s;
                    if (tt < TC + 2) {
                        int t = t0 - 1 + tt;
                        float v = 0.f;
                        if ((unsigned)t < (unsigned)FEAT) {
                            v = __fmul_rn(wa, xs[t]);
                            v = __fmaf_rn(wb, xs[t+1], v);
                            v = __fmaf_rn(wc, xs[t+2], v);
                            v = fmaxf(__fadd_rn(v, bb1), 0.f);
                        }
                        r1s2[gcc*RSP + tt] = splat2(v);   // pre-splatted {v,v}
                    }
                }
            }

            #pragma unroll
            for (int k = 0; k < 3; k++) {
                __syncthreads();   // w2 tile buffer free (and r1 ready at k=0)
                {   // stage 64x128 w2t tile (contiguous 32 KB)
                    const float4* src = (const float4*)(g_w2t + (size_t)(k*HID + g*CG)*LAT);
                    float4* dst = (float4*)(sm + W2T_O);
                    #pragma unroll
                    for (int r = 0; r < 8; r++) dst[tid + r*256] = src[tid + r*256];
                }
                __syncthreads();

                #pragma unroll 2
                for (int kk = 0; kk < CG; kk++) {
                    ulonglong2 a2 = wt[kk*32 + lane];   // w2[l0..l0+3], LDS.128
                    const ulonglong2* brow =
                        (const ulonglong2*)(r1s2 + kk*RSP) + w8*8;
                    #pragma unroll
                    for (int j = 0; j < 9; j++) {
                        ulonglong2 bb = brow[j];         // broadcast LDS.128
                        const int i0 = 2*j - k;          // compile-time per k
                        const int i1 = 2*j + 1 - k;
                        if (i0 >= 0 && i0 < 16) {
                            acc[0][i0] = ffma2(a2.x, bb.x, acc[0][i0]);
                            acc[1][i0] = ffma2(a2.y, bb.x, acc[1][i0]);
                        }
                        if (i1 >= 0 && i1 < 16) {
                            acc[0][i1] = ffma2(a2.x, bb.y, acc[0][i1]);
                            acc[1][i1] = ffma2(a2.y, bb.y, acc[1][i1]);
                        }
                    }
                }
            }
        }

        // relu(conv2 + b2), masked fp64 accumulation toward the mean
        #pragma unroll
        for (int i = 0; i < 16; i++) {
            if (t0 + w8*16 + i < FEAT) {
                #pragma unroll
                for (int p = 0; p < 2; p++) {
                    float2 f = unpack2(acc[p][i]);
                    zp[2*p+0] += (double)fmaxf(__fadd_rn(f.x, bl[2*p+0]), 0.f);
                    zp[2*p+1] += (double)fmaxf(__fadd_rn(f.y, bl[2*p+1]), 0.f);
                }
            }
        }
    }

    // cross-warp fp64 reduce (fixed order), then mean
    __syncthreads();
    double* dp = (double*)(sm + R1_O);   // overlaps r1s2 (dead)
    #pragma unroll
    for (int j = 0; j < 4; j++) dp[w8*128 + l0 + j] = zp[j];
    __syncthreads();
    if (tid < LAT) {
        double v = dp[tid];
        #pragma unroll
        for (int w = 1; w < 8; w++) v += dp[w*128 + tid];
        g_z[(size_t)b*LAT + tid] = __fdiv_rn((float)v, (float)FEAT);
    }
}

// ---------------------------------------------------------------------------
// RVQ (verbatim from the passing kernel)
// ---------------------------------------------------------------------------
__global__ void __launch_bounds__(256)
rvq_kernel(const float* __restrict__ cb,
           float* __restrict__ out_zq, float* __restrict__ out_idx,
           int write_zq, int write_idx)
{
    __shared__ __align__(16) float res[8][LAT];
    __shared__ int sidx[8][NQ];

    const int tid  = threadIdx.x;
    const int w    = tid >> 5;
    const int lane = tid & 31;
    const int b    = blockIdx.x * 8 + w;

    float qs[4] = {0.f, 0.f, 0.f, 0.f};
    #pragma unroll
    for (int m = 0; m < 4; m++)
        res[w][lane + 32*m] = g_z[(size_t)b*LAT + lane + 32*m];
    __syncwarp();

    for (int q = 0; q < NQ; q++) {
        const float* cbq = cb + (size_t)q*NEMB*LAT;
        const float* cnq = g_cnorm + q*NEMB;

        float A;
        {
            float sA = 0.f;
            #pragma unroll
            for (int m = 0; m < 4; m++) {
                float rv = res[w][lane + 32*m];
                sA = __fmaf_rn(rv, rv, sA);
            }
            #pragma unroll
            for (int off = 16; off > 0; off >>= 1)
                sA = __fadd_rn(sA, __shfl_xor_sync(0xffffffffu, sA, off));
            A = sA;
        }

        float best = CUDART_INF_F;
        int   bj   = 0x7fffffff;
        #pragma unroll 1
        for (int jj = 0; jj < NEMB/32; jj++) {
            const int j = (lane << 4) + jj;
            const float4* crow = (const float4*)(cbq + (size_t)j*LAT);
            const float4* rrow = (const float4*)(res[w]);
            float dot = 0.f;
            #pragma unroll
            for (int m = 0; m < LAT/4; m++) {
                float4 cv = crow[m];
                float4 rv = rrow[m];
                dot = __fmaf_rn(cv.x, rv.x, dot);
                dot = __fmaf_rn(cv.y, rv.y, dot);
                dot = __fmaf_rn(cv.z, rv.z, dot);
                dot = __fmaf_rn(cv.w, rv.w, dot);
            }
            float t1 = __fmaf_rn(-2.f, dot, A);
            float d  = __fadd_rn(t1, cnq[j]);
            if (d < best || (d == best && j < bj)) { best = d; bj = j; }
        }
        #pragma unroll
        for (int off = 16; off > 0; off >>= 1) {
            float ob = __shfl_xor_sync(0xffffffffu, best, off);
            int   oj = __shfl_xor_sync(0xffffffffu, bj,   off);
            if (ob < best || (ob == best && oj < bj)) { best = ob; bj = oj; }
        }
        if (lane == 0) sidx[w][q] = bj;

        #pragma unroll
        for (int m = 0; m < 4; m++) {
            int d = lane + 32*m;
            float c = cbq[(size_t)bj*LAT + d];
            res[w][d] = __fadd_rn(res[w][d], -c);
            qs[m] = __fadd_rn(qs[m], c);
        }
        __syncwarp();
    }

    if (write_zq) {
        #pragma unroll
        for (int m = 0; m < 4; m++)
            out_zq[(size_t)b*LAT + lane + 32*m] = qs[m];
    }
    if (write_idx && lane < NQ)
        out_idx[(size_t)b*NQ + lane] = (float)sidx[w][lane];
}

// ---------------------------------------------------------------------------
extern "C" void kernel_launch(void* const* d_in, const int* in_sizes, int n_in,
                              void* d_out, int out_size)
{
    const float* x  = (const float*)d_in[0];
    const float* w1 = (const float*)d_in[1];
    const float* b1 = (const float*)d_in[2];
    const float* w2 = (const float*)d_in[3];
    const float* b2 = (const float*)d_in[4];
    const float* cb = (const float*)d_in[5];

    cudaFuncSetAttribute(encoder_kernel,
                         cudaFuncAttributeMaxDynamicSharedMemorySize,
                         ENC_SMEM_BYTES);

    const int total = (KTOT*LAT) + (NQ*NEMB);
    prep_kernel<<<(total + 255)/256, 256>>>(w2, cb);
    encoder_kernel<<<B_SZ, 256, ENC_SMEM_BYTES>>>(x, w1, b1, b2);

    float* out_zq  = (float*)d_out;
    float* out_idx = (float*)d_out + (size_t)B_SZ*LAT;
    int write_zq = 1, write_idx = 1;
    if (out_size >= B_SZ*(LAT + NQ)) {
        // both
    } else if (out_size >= B_SZ*LAT) {
        write_idx = 0;
    } else {
        write_zq = 0;
        out_idx  = (float*)d_out;
    }
    rvq_kernel<<<B_SZ/8, 256>>>(cb, out_zq, out_idx, write_zq, write_idx);
}

// round 9
// speedup vs baseline: 1.6191x; 1.2546x over previous
#include <cuda_runtime.h>
#include <cuda_bf16.h>
#include <math_constants.h>
#include <cstdint>

#define B_SZ  2048
#define FEAT  840
#define HID   256
#define LAT   128
#define NQ    12
#define NEMB  512
#define KTOT  768

#define NT        7
#define TILE_T    128
#define TILES_TOT (B_SZ*NT)           /* 14336 */
#define NCHK      24
#define CHUNK_U32 6144
#define NBFRAG    (NCHK*CHUNK_U32)    /* 147456 */

#define MARGIN 1e-6f

typedef unsigned long long ull;

// ----------------------------- device scratch ------------------------------
__device__ __align__(16) uint32_t g_Bfrag[NBFRAG];   // w2 bf16 3-split frags
__device__ __align__(16) float g_w2t[KTOT*LAT];      // exact path [(k*256+c)][l]
__device__ float  g_cnorm[NQ*NEMB];
__device__ double g_zpart[(size_t)TILES_TOT*LAT];
__device__ __align__(16) float g_z[B_SZ*LAT];
__device__ int g_flagcnt;
__device__ int g_flaglist[B_SZ];

// exact 3-way bf16 split
__device__ __forceinline__ float bf16_split_val(float v, int split){
    float h = __bfloat162float(__float2bfloat16_rn(v));
    if (split == 0) return h;
    float r = v - h;
    float m = __bfloat162float(__float2bfloat16_rn(r));
    if (split == 1) return m;
    return r - m;
}

__device__ __forceinline__ void mma_bf16(float* d, const uint32_t* a, const uint32_t* b){
    asm volatile(
        "mma.sync.aligned.m16n8k16.row.col.f32.bf16.bf16.f32 "
        "{%0,%1,%2,%3}, {%4,%5,%6,%7}, {%8,%9}, {%0,%1,%2,%3};"
        : "+f"(d[0]), "+f"(d[1]), "+f"(d[2]), "+f"(d[3])
        : "r"(a[0]), "r"(a[1]), "r"(a[2]), "r"(a[3]), "r"(b[0]), "r"(b[1]));
}

// ------------------------------- prep kernel -------------------------------
__global__ void prep_kernel(const float* __restrict__ w2,
                            const float* __restrict__ cb)
{
    int i = blockIdx.x * blockDim.x + threadIdx.x;
    if (i == 0) g_flagcnt = 0;
    if (i < NBFRAG) {
        int reg   = i & 1;
        int lane  = (i >> 1) & 31;
        int nt    = (i >> 6) & 15;
        int ks    = (i >> 10) & 1;
        int t     = i >> 11;
        int split = t % 3;
        int s     = t / 3;
        int gr = lane >> 2, gc = lane & 3;
        int l  = nt*8 + gr;
        int tap = s >> 3;
        int c0 = (s & 7)*32 + ks*16 + gc*2 + reg*8;
        float v0 = w2[l*768 + c0*3 + tap];
        float v1 = w2[l*768 + (c0+1)*3 + tap];
        uint32_t lo = (uint32_t)__bfloat16_as_ushort(__float2bfloat16_rn(bf16_split_val(v0, split)));
        uint32_t hi = (uint32_t)__bfloat16_as_ushort(__float2bfloat16_rn(bf16_split_val(v1, split)));
        g_Bfrag[i] = lo | (hi << 16);
    } else if (i < NBFRAG + KTOT*LAT) {
        int j = i - NBFRAG;
        int l  = j & 127;
        int kk = j >> 7;
        int c  = kk & 255;
        int k  = kk >> 8;
        g_w2t[j] = w2[l*KTOT + c*3 + k];
    } else {
        int j = i - NBFRAG - KTOT*LAT;
        if (j < NQ*NEMB) {
            const float4* row = (const float4*)(cb + (size_t)j*LAT);
            float s = 0.f;
            #pragma unroll
            for (int m = 0; m < LAT/4; m++) {
                float4 v = row[m];
                s = __fmaf_rn(v.x, v.x, s);
                s = __fmaf_rn(v.y, v.y, s);
                s = __fmaf_rn(v.z, v.z, s);
                s = __fmaf_rn(v.w, v.w, s);
            }
            g_cnorm[j] = s;
        }
    }
}

// ------------------------- fast encoder (bf16 x6 mma) ----------------------
#define FXS_O   0
#define FW1_O   136
#define FB1_O   (136+768)
#define FB2_O   (136+768+256)
#define FA_O    1288
#define FB_O    (FA_O + 6144)
#define FAST_SMEM_FLOATS (FB_O + 6144)
#define FAST_SMEM_BYTES  (FAST_SMEM_FLOATS*4)

__global__ void __launch_bounds__(256, 2)
encoder_fast(const float* __restrict__ x,  const float* __restrict__ w1,
             const float* __restrict__ b1, const float* __restrict__ b2)
{
    extern __shared__ float sm[];
    uint32_t* Asm = (uint32_t*)(sm + FA_O);
    uint32_t* Bsm = (uint32_t*)(sm + FB_O);
    unsigned short* Ah16 = (unsigned short*)Asm;

    const int tid  = threadIdx.x;
    const int lane = tid & 31;
    const int wid  = tid >> 5;
    const int wm   = wid & 3;
    const int wn   = wid >> 2;

    const int g  = blockIdx.x;
    const int b  = g / NT;
    const int t0 = (g % NT) * TILE_T;

    if (tid < 136) {
        int t = t0 - 2 + tid;
        sm[FXS_O + tid] = ((unsigned)t < (unsigned)FEAT)
                        ? x[(size_t)b*FEAT + t] : 0.f;
    }
    for (int i = tid; i < HID*3; i += 256) sm[FW1_O + i] = w1[i];
    if (tid < HID) sm[FB1_O + tid] = b1[tid];
    if (tid < LAT) sm[FB2_O + tid] = b2[tid];

    float acc[2][8][4];
    #pragma unroll
    for (int mi = 0; mi < 2; mi++)
        #pragma unroll
        for (int j = 0; j < 8; j++)
            #pragma unroll
            for (int r = 0; r < 4; r++) acc[mi][j][r] = 0.f;

    const int kk      = tid & 31;
    const int trow0   = tid >> 5;
    const int ksg     = kk >> 4;
    const int kin16   = kk & 15;
    const int gc2     = (kin16 & 7) >> 1;
    const int halfsel = kin16 & 1;
    const int regk    = (kin16 >= 8) ? 2 : 0;

    __syncthreads();

    for (int s = 0; s < NCHK; s++) {
        const int tap = s >> 3;
        const int c0  = (s & 7) * 32;
        __syncthreads();

        {
            const uint4* src = (const uint4*)(g_Bfrag + s*CHUNK_U32);
            uint4* dst = (uint4*)Bsm;
            #pragma unroll
            for (int r = 0; r < 6; r++) dst[tid + r*256] = src[tid + r*256];
        }

        {
            const int c   = c0 + kk;
            const float wa = sm[FW1_O + c*3 + 0];
            const float wb = sm[FW1_O + c*3 + 1];
            const float wc = sm[FW1_O + c*3 + 2];
            const float bb = sm[FB1_O + c];
            #pragma unroll
            for (int e = 0; e < 16; e++) {
                const int tl = trow0 + e*8;
                const int u  = t0 + tl + tap - 1;
                float v = 0.f;
                if ((unsigned)u < (unsigned)FEAT) {
                    const float* xp = sm + FXS_O + tl + tap;
                    v = __fmul_rn(wa, xp[0]);
                    v = __fmaf_rn(wb, xp[1], v);
                    v = __fmaf_rn(wc, xp[2], v);
                    v = fmaxf(__fadd_rn(v, bb), 0.f);
                }
                float hf = __bfloat162float(__float2bfloat16_rn(v));
                float r1 = v - hf;
                float mf = __bfloat162float(__float2bfloat16_rn(r1));
                float lf = r1 - mf;

                const int mt   = e >> 1;
                const int regm = e & 1;
                const int reg  = regm + regk;
                const int lanep = trow0*4 + gc2;
                const int wbase = (ksg*8 + mt)*128 + lanep*4 + reg;
                const int u16i  = wbase*2 + halfsel;
                Ah16[u16i]          = __bfloat16_as_ushort(__float2bfloat16_rn(hf));
                Ah16[u16i + 2*2048] = __bfloat16_as_ushort(__float2bfloat16_rn(mf));
                Ah16[u16i + 4*2048] = __bfloat16_as_ushort(__float2bfloat16_rn(lf));
            }
        }
        __syncthreads();

        #pragma unroll
        for (int ks = 0; ks < 2; ks++) {
            uint32_t aH[2][4], aM[2][4], aL[2][4];
            #pragma unroll
            for (int mi = 0; mi < 2; mi++) {
                const int mt = wm*2 + mi;
                const int base = (ks*8 + mt)*128 + lane*4;
                uint4 h = *(const uint4*)(Asm + base);
                uint4 m = *(const uint4*)(Asm + 2048 + base);
                uint4 l = *(const uint4*)(Asm + 4096 + base);
                aH[mi][0]=h.x; aH[mi][1]=h.y; aH[mi][2]=h.z; aH[mi][3]=h.w;
                aM[mi][0]=m.x; aM[mi][1]=m.y; aM[mi][2]=m.z; aM[mi][3]=m.w;
                aL[mi][0]=l.x; aL[mi][1]=l.y; aL[mi][2]=l.z; aL[mi][3]=l.w;
            }
            #pragma unroll
            for (int j = 0; j < 8; j++) {
                const int nt = wn*8 + j;
                const int bbase = (ks*16 + nt)*32*2 + lane*2;
                uint2 h2 = *(const uint2*)(Bsm + bbase);
                uint2 m2 = *(const uint2*)(Bsm + 2048 + bbase);
                uint2 l2 = *(const uint2*)(Bsm + 4096 + bbase);
                uint32_t bH[2] = {h2.x, h2.y};
                uint32_t bM[2] = {m2.x, m2.y};
                uint32_t bL[2] = {l2.x, l2.y};
                #pragma unroll
                for (int mi = 0; mi < 2; mi++) {
                    mma_bf16(acc[mi][j], aH[mi], bH);
                    mma_bf16(acc[mi][j], aH[mi], bM);
                    mma_bf16(acc[mi][j], aM[mi], bH);
                    mma_bf16(acc[mi][j], aH[mi], bL);
                    mma_bf16(acc[mi][j], aL[mi], bH);
                    mma_bf16(acc[mi][j], aM[mi], bM);
                }
            }
        }
    }

    __syncthreads();
    double* dpart = (double*)(sm + FA_O);

    const int qrow = lane >> 2;
    const int qcol = lane & 3;
    #pragma unroll
    for (int j = 0; j < 8; j++) {
        double s0 = 0.0, s1 = 0.0;
        const int l0 = wn*64 + j*8 + 2*qcol;
        const float bz0 = sm[FB2_O + l0];
        const float bz1 = sm[FB2_O + l0 + 1];
        #pragma unroll
        for (int mi = 0; mi < 2; mi++) {
            const int ra  = t0 + wm*32 + mi*16 + qrow;
            const int rb2 = ra + 8;
            if (ra < FEAT) {
                s0 += (double)fmaxf(__fadd_rn(acc[mi][j][0], bz0), 0.f);
                s1 += (double)fmaxf(__fadd_rn(acc[mi][j][1], bz1), 0.f);
            }
            if (rb2 < FEAT) {
                s0 += (double)fmaxf(__fadd_rn(acc[mi][j][2], bz0), 0.f);
                s1 += (double)fmaxf(__fadd_rn(acc[mi][j][3], bz1), 0.f);
            }
        }
        #pragma unroll
        for (int off = 4; off < 32; off <<= 1) {
            s0 += __shfl_xor_sync(0xffffffffu, s0, off);
            s1 += __shfl_xor_sync(0xffffffffu, s1, off);
        }
        if (qrow == 0) {
            dpart[wm*128 + l0]     = s0;
            dpart[wm*128 + l0 + 1] = s1;
        }
    }
    __syncthreads();
    if (tid < LAT) {
        double z = ((dpart[tid] + dpart[128 + tid]) + dpart[256 + tid]) + dpart[384 + tid];
        g_zpart[(size_t)g*LAT + tid] = z;
    }
}

// --------------------------- fast z reduce ---------------------------------
__global__ void reduce_kernel()
{
    int idx = blockIdx.x * blockDim.x + threadIdx.x;
    if (idx >= B_SZ*LAT) return;
    int b = idx >> 7, l = idx & 127;
    double s = 0.0;
    #pragma unroll
    for (int t = 0; t < NT; t++)
        s += g_zpart[(size_t)(b*NT + t)*LAT + l];
    g_z[idx] = __fdiv_rn((float)s, (float)FEAT);
}

// --------------------- RVQ core (proven, inlined) ---------------------------
// flag_mode: 1 = track second-best gap and flag rows under MARGIN
__device__ __forceinline__ void rvq_row(const float* __restrict__ cb,
                                        float* res, float* qs, int* sidx,
                                        int lane, int flag_mode, int b_row)
{
    bool flagged = false;

    for (int q = 0; q < NQ; q++) {
        const float* cbq = cb + (size_t)q*NEMB*LAT;
        const float* cnq = g_cnorm + q*NEMB;

        float A;
        {
            float sA = 0.f;
            #pragma unroll
            for (int m = 0; m < 4; m++) {
                float rv = res[lane + 32*m];
                sA = __fmaf_rn(rv, rv, sA);
            }
            #pragma unroll
            for (int off = 16; off > 0; off >>= 1)
                sA = __fadd_rn(sA, __shfl_xor_sync(0xffffffffu, sA, off));
            A = sA;
        }

        float b1v = CUDART_INF_F, b2v = CUDART_INF_F;
        int   j1  = 0x7fffffff;
        #pragma unroll 1
        for (int jj = 0; jj < NEMB/32; jj++) {
            const int j = (lane << 4) + jj;
            const float4* crow = (const float4*)(cbq + (size_t)j*LAT);
            const float4* rrow = (const float4*)res;
            float dot = 0.f;
            #pragma unroll
            for (int m = 0; m < LAT/4; m++) {
                float4 cv = crow[m];
                float4 rv = rrow[m];
                dot = __fmaf_rn(cv.x, rv.x, dot);
                dot = __fmaf_rn(cv.y, rv.y, dot);
                dot = __fmaf_rn(cv.z, rv.z, dot);
                dot = __fmaf_rn(cv.w, rv.w, dot);
            }
            float t1 = __fmaf_rn(-2.f, dot, A);
            float d  = __fadd_rn(t1, cnq[j]);
            if (d < b1v) { b2v = b1v; b1v = d; j1 = j; }
            else if (d < b2v) { b2v = d; }
        }
        #pragma unroll
        for (int off = 16; off > 0; off >>= 1) {
            float ob1 = __shfl_xor_sync(0xffffffffu, b1v, off);
            int   oj1 = __shfl_xor_sync(0xffffffffu, j1,  off);
            float ob2 = __shfl_xor_sync(0xffffffffu, b2v, off);
            if (ob1 < b1v || (ob1 == b1v && oj1 < j1)) {
                b2v = fminf(b1v, ob2);
                b1v = ob1; j1 = oj1;
            } else {
                b2v = fminf(b2v, ob1);
            }
        }
        if (flag_mode && (b2v - b1v) < MARGIN) flagged = true;
        if (lane == 0) sidx[q] = j1;

        #pragma unroll
        for (int m = 0; m < 4; m++) {
            int d = lane + 32*m;
            float c = cbq[(size_t)j1*LAT + d];
            res[d] = __fadd_rn(res[d], -c);
            qs[m] = __fadd_rn(qs[m], c);
        }
        __syncwarp();
    }

    if (flag_mode && flagged && lane == 0) {
        int pos = atomicAdd(&g_flagcnt, 1);
        g_flaglist[pos] = b_row;
    }
}

// --------------------- RVQ pass 1 (fast z, flags) ---------------------------
__global__ void __launch_bounds__(256)
rvq_flag(const float* __restrict__ cb,
         float* __restrict__ out_zq, float* __restrict__ out_idx,
         int write_zq, int write_idx)
{
    __shared__ __align__(16) float res[8][LAT];
    __shared__ int sidx[8][NQ];

    const int tid  = threadIdx.x;
    const int w    = tid >> 5;
    const int lane = tid & 31;
    const int b    = blockIdx.x * 8 + w;

    float qs[4] = {0.f, 0.f, 0.f, 0.f};
    #pragma unroll
    for (int m = 0; m < 4; m++)
        res[w][lane + 32*m] = g_z[(size_t)b*LAT + lane + 32*m];
    __syncwarp();

    rvq_row(cb, res[w], qs, sidx[w], lane, 1, b);

    if (write_zq) {
        #pragma unroll
        for (int m = 0; m < 4; m++)
            out_zq[(size_t)b*LAT + lane + 32*m] = qs[m];
    }
    if (write_idx && lane < NQ)
        out_idx[(size_t)b*NQ + lane] = (float)sidx[w][lane];
}

// -------------------- exact encoder chunk (bit-exact chain) -----------------
#define TCX   128
#define CG    64
#define RSP   132
#define EXS_O   0
#define EW1_O   844
#define EB1_O   (844+768)
#define ER1_O   (844+768+256)
#define EW2T_O  (ER1_O + CG*RSP*2)
#define EX_SMEM_FLOATS (EW2T_O + CG*LAT)
#define EX_SMEM_BYTES  (EX_SMEM_FLOATS*4)

__device__ __forceinline__ ull ffma2(ull a, ull b, ull c){
    ull d;
    asm("fma.rn.f32x2 %0, %1, %2, %3;" : "=l"(d) : "l"(a), "l"(b), "l"(c));
    return d;
}
__device__ __forceinline__ float2 unpack2(ull v){
    float2 f; asm("mov.b64 {%0,%1}, %2;" : "=f"(f.x), "=f"(f.y) : "l"(v));
    return f;
}
__device__ __forceinline__ ull splat2(float v){
    ull d; asm("mov.b64 %0, {%1,%1};" : "=l"(d) : "f"(v));
    return d;
}

__global__ void __launch_bounds__(256, 2)
exact_chunk(const float* __restrict__ x,  const float* __restrict__ w1,
            const float* __restrict__ b1, const float* __restrict__ b2)
{
    const int cnt = g_flagcnt;
    const int i   = blockIdx.x;
    if (i >= cnt * NT) return;
    const int b  = g_flaglist[i / NT];
    const int ch = i % NT;

    extern __shared__ float sm[];
    float* xs  = sm + EXS_O;
    float* w1s = sm + EW1_O;
    float* b1s = sm + EB1_O;
    ull*   r1s2 = (ull*)(sm + ER1_O);
    const ulonglong2* wt = (const ulonglong2*)(sm + EW2T_O);

    const int tid  = threadIdx.x;
    const int lane = tid & 31;
    const int w8   = tid >> 5;
    const int l0   = lane * 4;
    const int gcc  = tid >> 2;
    const int gsub = tid & 3;

    for (int ii = tid; ii < FEAT; ii += 256) xs[ii + 1] = x[(size_t)b*FEAT + ii];
    for (int ii = tid; ii < HID*3; ii += 256) w1s[ii] = w1[ii];
    if (tid < HID) b1s[tid] = b1[tid];
    if (tid == 0) { xs[0] = 0.f; xs[FEAT + 1] = 0.f; xs[FEAT + 2] = 0.f; }

    float bl[4];
    #pragma unroll
    for (int j = 0; j < 4; j++) bl[j] = b2[l0 + j];

    double zp[4] = {0.0, 0.0, 0.0, 0.0};
    __syncthreads();

    const int t0 = ch * TCX;

    ull acc[2][16];
    #pragma unroll
    for (int p = 0; p < 2; p++)
        #pragma unroll
        for (int ii = 0; ii < 16; ii++) acc[p][ii] = 0ull;

    for (int g = 0; g < 4; g++) {
        __syncthreads();
        {
            const int c  = g*CG + gcc;
            const float wa = w1s[c*3+0], wb = w1s[c*3+1], wc = w1s[c*3+2];
            const float bb1 = b1s[c];
            #pragma unroll
            for (int s = 0; s < 33; s++) {
                int tt = gsub + 4*s;
                if (tt < TCX + 2) {
                    int t = t0 - 1 + tt;
                    float v = 0.f;
                    if ((unsigned)t < (unsigned)FEAT) {
                        v = __fmul_rn(wa, xs[t]);
                        v = __fmaf_rn(wb, xs[t+1], v);
                        v = __fmaf_rn(wc, xs[t+2], v);
                        v = fmaxf(__fadd_rn(v, bb1), 0.f);
                    }
                    r1s2[gcc*RSP + tt] = splat2(v);
                }
            }
        }

        #pragma unroll
        for (int k = 0; k < 3; k++) {
            __syncthreads();
            {
                const float4* src = (const float4*)(g_w2t + (size_t)(k*HID + g*CG)*LAT);
                float4* dst = (float4*)(sm + EW2T_O);
                #pragma unroll
                for (int r = 0; r < 8; r++) dst[tid + r*256] = src[tid + r*256];
            }
            __syncthreads();

            #pragma unroll 2
            for (int kk = 0; kk < CG; kk++) {
                ulonglong2 a2 = wt[kk*32 + lane];
                const ulonglong2* brow =
                    (const ulonglong2*)(r1s2 + kk*RSP) + w8*8;
                #pragma unroll
                for (int j = 0; j < 9; j++) {
                    ulonglong2 bb = brow[j];
                    const int i0 = 2*j - k;
                    const int i1 = 2*j + 1 - k;
                    if (i0 >= 0 && i0 < 16) {
                        acc[0][i0] = ffma2(a2.x, bb.x, acc[0][i0]);
                        acc[1][i0] = ffma2(a2.y, bb.x, acc[1][i0]);
                    }
                    if (i1 >= 0 && i1 < 16) {
                        acc[0][i1] = ffma2(a2.x, bb.y, acc[0][i1]);
                        acc[1][i1] = ffma2(a2.y, bb.y, acc[1][i1]);
                    }
                }
            }
        }
    }

    #pragma unroll
    for (int ii = 0; ii < 16; ii++) {
        if (t0 + w8*16 + ii < FEAT) {
            #pragma unroll
            for (int p = 0; p < 2; p++) {
                float2 f = unpack2(acc[p][ii]);
                zp[2*p+0] += (double)fmaxf(__fadd_rn(f.x, bl[2*p+0]), 0.f);
                zp[2*p+1] += (double)fmaxf(__fadd_rn(f.y, bl[2*p+1]), 0.f);
            }
        }
    }

    __syncthreads();
    double* dp = (double*)(sm + ER1_O);
    #pragma unroll
    for (int j = 0; j < 4; j++) dp[w8*128 + l0 + j] = zp[j];
    __syncthreads();
    if (tid < LAT) {
        double v = dp[tid];
        #pragma unroll
        for (int w = 1; w < 8; w++) v += dp[w*128 + tid];
        g_zpart[(size_t)(b*NT + ch)*LAT + tid] = v;   // overwrite fast partial
    }
}

// --------------------- fixed rows: reduce + RVQ redo ------------------------
__global__ void fix_reduce()
{
    int idx = blockIdx.x * blockDim.x + threadIdx.x;   // up to 2048*128
    int p = idx >> 7;
    if (p >= g_flagcnt) return;
    int b = g_flaglist[p];
    int l = idx & 127;
    double s = 0.0;
    #pragma unroll
    for (int t = 0; t < NT; t++)
        s += g_zpart[(size_t)(b*NT + t)*LAT + l];
    g_z[(size_t)b*LAT + l] = __fdiv_rn((float)s, (float)FEAT);
}

__global__ void __launch_bounds__(256)
rvq_fix(const float* __restrict__ cb,
        float* __restrict__ out_zq, float* __restrict__ out_idx,
        int write_zq, int write_idx)
{
    __shared__ __align__(16) float res[8][LAT];
    __shared__ int sidx[8][NQ];

    const int tid  = threadIdx.x;
    const int w    = tid >> 5;
    const int lane = tid & 31;
    const int slot = blockIdx.x * 8 + w;
    if (slot >= g_flagcnt) return;
    const int b = g_flaglist[slot];

    float qs[4] = {0.f, 0.f, 0.f, 0.f};
    #pragma unroll
    for (int m = 0; m < 4; m++)
        res[w][lane + 32*m] = g_z[(size_t)b*LAT + lane + 32*m];
    __syncwarp();

    rvq_row(cb, res[w], qs, sidx[w], lane, 0, b);

    if (write_zq) {
        #pragma unroll
        for (int m = 0; m < 4; m++)
            out_zq[(size_t)b*LAT + lane + 32*m] = qs[m];
    }
    if (write_idx && lane < NQ)
        out_idx[(size_t)b*NQ + lane] = (float)sidx[w][lane];
}

// ---------------------------------------------------------------------------
extern "C" void kernel_launch(void* const* d_in, const int* in_sizes, int n_in,
                              void* d_out, int out_size)
{
    const float* x  = (const float*)d_in[0];
    const float* w1 = (const float*)d_in[1];
    const float* b1 = (const float*)d_in[2];
    const float* w2 = (const float*)d_in[3];
    const float* b2 = (const float*)d_in[4];
    const float* cb = (const float*)d_in[5];

    cudaFuncSetAttribute(encoder_fast,
                         cudaFuncAttributeMaxDynamicSharedMemorySize,
                         FAST_SMEM_BYTES);
    cudaFuncSetAttribute(exact_chunk,
                         cudaFuncAttributeMaxDynamicSharedMemorySize,
                         EX_SMEM_BYTES);

    float* out_zq  = (float*)d_out;
    float* out_idx = (float*)d_out + (size_t)B_SZ*LAT;
    int write_zq = 1, write_idx = 1;
    if (out_size >= B_SZ*(LAT + NQ)) {
    } else if (out_size >= B_SZ*LAT) {
        write_idx = 0;
    } else {
        write_zq = 0;
        out_idx  = (float*)d_out;
    }

    const int total = NBFRAG + KTOT*LAT + NQ*NEMB;     // 251904
    prep_kernel<<<(total + 255)/256, 256>>>(w2, cb);
    encoder_fast<<<TILES_TOT, 256, FAST_SMEM_BYTES>>>(x, w1, b1, b2);
    reduce_kernel<<<(B_SZ*LAT + 255)/256, 256>>>();
    rvq_flag<<<B_SZ/8, 256>>>(cb, out_zq, out_idx, write_zq, write_idx);
    exact_chunk<<<TILES_TOT, 256, EX_SMEM_BYTES>>>(x, w1, b1, b2);
    fix_reduce<<<(B_SZ*LAT + 255)/256, 256>>>();
    rvq_fix<<<B_SZ/8, 256>>>(cb, out_zq, out_idx, write_zq, write_idx);
}

// round 10
// speedup vs baseline: 2.1048x; 1.3000x over previous
#include <cuda_runtime.h>
#include <cuda_fp16.h>
#include <math_constants.h>
#include <cstdint>

#define B_SZ  2048
#define FEAT  840
#define HID   256
#define LAT   128
#define NQ    12
#define NEMB  512
#define KTOT  768

#define NT        7
#define TILE_T    128
#define TILES_TOT (B_SZ*NT)           /* 14336 */
#define NCHK      24
#define CHUNK_U32 4096                /* B frag words per chunk: 2*2*16*32*2 */
#define NBFRAG    (NCHK*CHUNK_U32)    /* 98304 */

#define MARGIN 3e-6f

typedef unsigned long long ull;

// ----------------------------- device scratch ------------------------------
__device__ __align__(16) uint32_t g_Bfrag[NBFRAG];   // w2 fp16 2-split frags
__device__ __align__(16) float g_w2t[KTOT*LAT];      // exact path [(k*256+c)][l]
__device__ float  g_cnorm[NQ*NEMB];
__device__ double g_zpart[(size_t)TILES_TOT*LAT];
__device__ __align__(16) float g_z[B_SZ*LAT];
__device__ int g_flagcnt;
__device__ int g_flaglist[B_SZ];

// fp16 2-way split: v ~= h + l  (residual ~2^-24 relative)
__device__ __forceinline__ float fp16_split_val(float v, int split){
    float h = __half2float(__float2half_rn(v));
    if (split == 0) return h;
    return v - h;   // caller converts to fp16 (one more rounding, bounded)
}

__device__ __forceinline__ void mma_fp16(float* d, const uint32_t* a, const uint32_t* b){
    asm volatile(
        "mma.sync.aligned.m16n8k16.row.col.f32.f16.f16.f32 "
        "{%0,%1,%2,%3}, {%4,%5,%6,%7}, {%8,%9}, {%0,%1,%2,%3};"
        : "+f"(d[0]), "+f"(d[1]), "+f"(d[2]), "+f"(d[3])
        : "r"(a[0]), "r"(a[1]), "r"(a[2]), "r"(a[3]), "r"(b[0]), "r"(b[1]));
}

// ------------------------------- prep kernel -------------------------------
// B layout (u32): [s(24)][split(2)][ks(2)][nt(16)][lane(32)][reg(2)]
__global__ void prep_kernel(const float* __restrict__ w2,
                            const float* __restrict__ cb)
{
    int i = blockIdx.x * blockDim.x + threadIdx.x;
    if (i == 0) g_flagcnt = 0;
    if (i < NBFRAG) {
        int reg   = i & 1;
        int lane  = (i >> 1) & 31;
        int nt    = (i >> 6) & 15;
        int ks    = (i >> 10) & 1;
        int split = (i >> 11) & 1;
        int s     = i >> 12;
        int gr = lane >> 2, gc = lane & 3;
        int l  = nt*8 + gr;
        int tap = s >> 3;
        int c0 = (s & 7)*32 + ks*16 + gc*2 + reg*8;
        float v0 = w2[l*768 + c0*3 + tap];
        float v1 = w2[l*768 + (c0+1)*3 + tap];
        uint32_t lo = (uint32_t)__half_as_ushort(__float2half_rn(fp16_split_val(v0, split)));
        uint32_t hi = (uint32_t)__half_as_ushort(__float2half_rn(fp16_split_val(v1, split)));
        g_Bfrag[i] = lo | (hi << 16);
    } else if (i < NBFRAG + KTOT*LAT) {
        int j = i - NBFRAG;
        int l  = j & 127;
        int kk = j >> 7;
        int c  = kk & 255;
        int k  = kk >> 8;
        g_w2t[j] = w2[l*KTOT + c*3 + k];
    } else {
        int j = i - NBFRAG - KTOT*LAT;
        if (j < NQ*NEMB) {
            const float4* row = (const float4*)(cb + (size_t)j*LAT);
            float s = 0.f;
            #pragma unroll
            for (int m = 0; m < LAT/4; m++) {
                float4 v = row[m];
                s = __fmaf_rn(v.x, v.x, s);
                s = __fmaf_rn(v.y, v.y, s);
                s = __fmaf_rn(v.z, v.z, s);
                s = __fmaf_rn(v.w, v.w, s);
            }
            g_cnorm[j] = s;
        }
    }
}

// ------------------------- fast encoder (fp16 x3 mma) ----------------------
#define FXS_O   0
#define FW1_O   136
#define FB1_O   (136+768)
#define FB2_O   (136+768+256)
#define FA_O    1288                  /* 4096 u32: [split(2)][ks(2)][mt(8)][lane(32)][reg(4)] */
#define FB_O    (FA_O + 4096)         /* 4096 u32 */
#define FAST_SMEM_FLOATS (FB_O + 4096)
#define FAST_SMEM_BYTES  (FAST_SMEM_FLOATS*4)

__global__ void __launch_bounds__(256, 2)
encoder_fast(const float* __restrict__ x,  const float* __restrict__ w1,
             const float* __restrict__ b1, const float* __restrict__ b2)
{
    extern __shared__ float sm[];
    uint32_t* Asm = (uint32_t*)(sm + FA_O);
    uint32_t* Bsm = (uint32_t*)(sm + FB_O);
    unsigned short* Ah16 = (unsigned short*)Asm;

    const int tid  = threadIdx.x;
    const int lane = tid & 31;
    const int wid  = tid >> 5;
    const int wm   = wid & 3;
    const int wn   = wid >> 2;

    const int g  = blockIdx.x;
    const int b  = g / NT;
    const int t0 = (g % NT) * TILE_T;

    if (tid < 136) {
        int t = t0 - 2 + tid;
        sm[FXS_O + tid] = ((unsigned)t < (unsigned)FEAT)
                        ? x[(size_t)b*FEAT + t] : 0.f;
    }
    for (int i = tid; i < HID*3; i += 256) sm[FW1_O + i] = w1[i];
    if (tid < HID) sm[FB1_O + tid] = b1[tid];
    if (tid < LAT) sm[FB2_O + tid] = b2[tid];

    float acc[2][8][4];
    #pragma unroll
    for (int mi = 0; mi < 2; mi++)
        #pragma unroll
        for (int j = 0; j < 8; j++)
            #pragma unroll
            for (int r = 0; r < 4; r++) acc[mi][j][r] = 0.f;

    const int kk      = tid & 31;
    const int trow0   = tid >> 5;
    const int ksg     = kk >> 4;
    const int kin16   = kk & 15;
    const int gc2     = (kin16 & 7) >> 1;
    const int halfsel = kin16 & 1;
    const int regk    = (kin16 >= 8) ? 2 : 0;

    __syncthreads();

    for (int s = 0; s < NCHK; s++) {
        const int tap = s >> 3;
        const int c0  = (s & 7) * 32;
        __syncthreads();

        {   // stage B fragments (16 KB contiguous copy)
            const uint4* src = (const uint4*)(g_Bfrag + s*CHUNK_U32);
            uint4* dst = (uint4*)Bsm;
            #pragma unroll
            for (int r = 0; r < 4; r++) dst[tid + r*256] = src[tid + r*256];
        }

        {   // generate A fragments: conv1 + relu + fp16 2-split
            const int c   = c0 + kk;
            const float wa = sm[FW1_O + c*3 + 0];
            const float wb = sm[FW1_O + c*3 + 1];
            const float wc = sm[FW1_O + c*3 + 2];
            const float bb = sm[FB1_O + c];
            #pragma unroll
            for (int e = 0; e < 16; e++) {
                const int tl = trow0 + e*8;
                const int u  = t0 + tl + tap - 1;
                float v = 0.f;
                if ((unsigned)u < (unsigned)FEAT) {
                    const float* xp = sm + FXS_O + tl + tap;
                    v = __fmul_rn(wa, xp[0]);
                    v = __fmaf_rn(wb, xp[1], v);
                    v = __fmaf_rn(wc, xp[2], v);
                    v = fmaxf(__fadd_rn(v, bb), 0.f);
                }
                __half hh = __float2half_rn(v);
                float  hf = __half2float(hh);
                __half lh = __float2half_rn(v - hf);

                const int mt   = e >> 1;
                const int regm = e & 1;
                const int reg  = regm + regk;
                const int lanep = trow0*4 + gc2;
                const int wbase = (ksg*8 + mt)*128 + lanep*4 + reg;
                const int u16i  = wbase*2 + halfsel;
                Ah16[u16i]          = __half_as_ushort(hh);
                Ah16[u16i + 4096]   = __half_as_ushort(lh);   // +2048 u32
            }
        }
        __syncthreads();

        #pragma unroll
        for (int ks = 0; ks < 2; ks++) {
            uint32_t aH[2][4], aL[2][4];
            #pragma unroll
            for (int mi = 0; mi < 2; mi++) {
                const int mt = wm*2 + mi;
                const int base = (ks*8 + mt)*128 + lane*4;
                uint4 h = *(const uint4*)(Asm + base);
                uint4 l = *(const uint4*)(Asm + 2048 + base);
                aH[mi][0]=h.x; aH[mi][1]=h.y; aH[mi][2]=h.z; aH[mi][3]=h.w;
                aL[mi][0]=l.x; aL[mi][1]=l.y; aL[mi][2]=l.z; aL[mi][3]=l.w;
            }
            #pragma unroll
            for (int j = 0; j < 8; j++) {
                const int nt = wn*8 + j;
                const int bbase = ((ks*16 + nt)*32 + lane)*2;
                uint2 h2 = *(const uint2*)(Bsm + bbase);
                uint2 l2 = *(const uint2*)(Bsm + 2048 + bbase);
                uint32_t bH[2] = {h2.x, h2.y};
                uint32_t bL[2] = {l2.x, l2.y};
                #pragma unroll
                for (int mi = 0; mi < 2; mi++) {
                    mma_fp16(acc[mi][j], aH[mi], bH);   // hh
                    mma_fp16(acc[mi][j], aH[mi], bL);   // hl
                    mma_fp16(acc[mi][j], aL[mi], bH);   // lh
                }
            }
        }
    }

    __syncthreads();
    double* dpart = (double*)(sm + FA_O);

    const int qrow = lane >> 2;
    const int qcol = lane & 3;
    #pragma unroll
    for (int j = 0; j < 8; j++) {
        double s0 = 0.0, s1 = 0.0;
        const int l0 = wn*64 + j*8 + 2*qcol;
        const float bz0 = sm[FB2_O + l0];
        const float bz1 = sm[FB2_O + l0 + 1];
        #pragma unroll
        for (int mi = 0; mi < 2; mi++) {
            const int ra  = t0 + wm*32 + mi*16 + qrow;
            const int rb2 = ra + 8;
            if (ra < FEAT) {
                s0 += (double)fmaxf(__fadd_rn(acc[mi][j][0], bz0), 0.f);
                s1 += (double)fmaxf(__fadd_rn(acc[mi][j][1], bz1), 0.f);
            }
            if (rb2 < FEAT) {
                s0 += (double)fmaxf(__fadd_rn(acc[mi][j][2], bz0), 0.f);
                s1 += (double)fmaxf(__fadd_rn(acc[mi][j][3], bz1), 0.f);
            }
        }
        #pragma unroll
        for (int off = 4; off < 32; off <<= 1) {
            s0 += __shfl_xor_sync(0xffffffffu, s0, off);
            s1 += __shfl_xor_sync(0xffffffffu, s1, off);
        }
        if (qrow == 0) {
            dpart[wm*128 + l0]     = s0;
            dpart[wm*128 + l0 + 1] = s1;
        }
    }
    __syncthreads();
    if (tid < LAT) {
        double z = ((dpart[tid] + dpart[128 + tid]) + dpart[256 + tid]) + dpart[384 + tid];
        g_zpart[(size_t)g*LAT + tid] = z;
    }
}

// --------------------------- fast z reduce ---------------------------------
__global__ void reduce_kernel()
{
    int idx = blockIdx.x * blockDim.x + threadIdx.x;
    if (idx >= B_SZ*LAT) return;
    int b = idx >> 7, l = idx & 127;
    double s = 0.0;
    #pragma unroll
    for (int t = 0; t < NT; t++)
        s += g_zpart[(size_t)(b*NT + t)*LAT + l];
    g_z[idx] = __fdiv_rn((float)s, (float)FEAT);
}

// --------------------- RVQ core (proven, inlined) ---------------------------
__device__ __forceinline__ void rvq_row(const float* __restrict__ cb,
                                        float* res, float* qs, int* sidx,
                                        int lane, int flag_mode, int b_row)
{
    bool flagged = false;

    for (int q = 0; q < NQ; q++) {
        const float* cbq = cb + (size_t)q*NEMB*LAT;
        const float* cnq = g_cnorm + q*NEMB;

        float A;
        {
            float sA = 0.f;
            #pragma unroll
            for (int m = 0; m < 4; m++) {
                float rv = res[lane + 32*m];
                sA = __fmaf_rn(rv, rv, sA);
            }
            #pragma unroll
            for (int off = 16; off > 0; off >>= 1)
                sA = __fadd_rn(sA, __shfl_xor_sync(0xffffffffu, sA, off));
            A = sA;
        }

        float b1v = CUDART_INF_F, b2v = CUDART_INF_F;
        int   j1  = 0x7fffffff;
        #pragma unroll 1
        for (int jj = 0; jj < NEMB/32; jj++) {
            const int j = (lane << 4) + jj;
            const float4* crow = (const float4*)(cbq + (size_t)j*LAT);
            const float4* rrow = (const float4*)res;
            float dot = 0.f;
            #pragma unroll
            for (int m = 0; m < LAT/4; m++) {
                float4 cv = crow[m];
                float4 rv = rrow[m];
                dot = __fmaf_rn(cv.x, rv.x, dot);
                dot = __fmaf_rn(cv.y, rv.y, dot);
                dot = __fmaf_rn(cv.z, rv.z, dot);
                dot = __fmaf_rn(cv.w, rv.w, dot);
            }
            float t1 = __fmaf_rn(-2.f, dot, A);
            float d  = __fadd_rn(t1, cnq[j]);
            if (d < b1v) { b2v = b1v; b1v = d; j1 = j; }
            else if (d < b2v) { b2v = d; }
        }
        #pragma unroll
        for (int off = 16; off > 0; off >>= 1) {
            float ob1 = __shfl_xor_sync(0xffffffffu, b1v, off);
            int   oj1 = __shfl_xor_sync(0xffffffffu, j1,  off);
            float ob2 = __shfl_xor_sync(0xffffffffu, b2v, off);
            if (ob1 < b1v || (ob1 == b1v && oj1 < j1)) {
                b2v = fminf(b1v, ob2);
                b1v = ob1; j1 = oj1;
            } else {
                b2v = fminf(b2v, ob1);
            }
        }
        if (flag_mode && (b2v - b1v) < MARGIN) flagged = true;
        if (lane == 0) sidx[q] = j1;

        #pragma unroll
        for (int m = 0; m < 4; m++) {
            int d = lane + 32*m;
            float c = cbq[(size_t)j1*LAT + d];
            res[d] = __fadd_rn(res[d], -c);
            qs[m] = __fadd_rn(qs[m], c);
        }
        __syncwarp();
    }

    if (flag_mode && flagged && lane == 0) {
        int pos = atomicAdd(&g_flagcnt, 1);
        g_flaglist[pos] = b_row;
    }
}

// --------------------- RVQ pass 1 (fast z, flags) ---------------------------
__global__ void __launch_bounds__(256)
rvq_flag(const float* __restrict__ cb,
         float* __restrict__ out_zq, float* __restrict__ out_idx,
         int write_zq, int write_idx)
{
    __shared__ __align__(16) float res[8][LAT];
    __shared__ int sidx[8][NQ];

    const int tid  = threadIdx.x;
    const int w    = tid >> 5;
    const int lane = tid & 31;
    const int b    = blockIdx.x * 8 + w;

    float qs[4] = {0.f, 0.f, 0.f, 0.f};
    #pragma unroll
    for (int m = 0; m < 4; m++)
        res[w][lane + 32*m] = g_z[(size_t)b*LAT + lane + 32*m];
    __syncwarp();

    rvq_row(cb, res[w], qs, sidx[w], lane, 1, b);

    if (write_zq) {
        #pragma unroll
        for (int m = 0; m < 4; m++)
            out_zq[(size_t)b*LAT + lane + 32*m] = qs[m];
    }
    if (write_idx && lane < NQ)
        out_idx[(size_t)b*NQ + lane] = (float)sidx[w][lane];
}

// -------------------- exact encoder chunk (bit-exact chain) -----------------
#define TCX   128
#define CG    64
#define RSP   132
#define EXS_O   0
#define EW1_O   844
#define EB1_O   (844+768)
#define ER1_O   (844+768+256)
#define EW2T_O  (ER1_O + CG*RSP*2)
#define EX_SMEM_FLOATS (EW2T_O + CG*LAT)
#define EX_SMEM_BYTES  (EX_SMEM_FLOATS*4)

__device__ __forceinline__ ull ffma2(ull a, ull b, ull c){
    ull d;
    asm("fma.rn.f32x2 %0, %1, %2, %3;" : "=l"(d) : "l"(a), "l"(b), "l"(c));
    return d;
}
__device__ __forceinline__ float2 unpack2(ull v){
    float2 f; asm("mov.b64 {%0,%1}, %2;" : "=f"(f.x), "=f"(f.y) : "l"(v));
    return f;
}
__device__ __forceinline__ ull splat2(float v){
    ull d; asm("mov.b64 %0, {%1,%1};" : "=l"(d) : "f"(v));
    return d;
}

__global__ void __launch_bounds__(256, 2)
exact_chunk(const float* __restrict__ x,  const float* __restrict__ w1,
            const float* __restrict__ b1, const float* __restrict__ b2)
{
    const int cnt = g_flagcnt;
    const int i   = blockIdx.x;
    if (i >= cnt * NT) return;
    const int b  = g_flaglist[i / NT];
    const int ch = i % NT;

    extern __shared__ float sm[];
    float* xs  = sm + EXS_O;
    float* w1s = sm + EW1_O;
    float* b1s = sm + EB1_O;
    ull*   r1s2 = (ull*)(sm + ER1_O);
    const ulonglong2* wt = (const ulonglong2*)(sm + EW2T_O);

    const int tid  = threadIdx.x;
    const int lane = tid & 31;
    const int w8   = tid >> 5;
    const int l0   = lane * 4;
    const int gcc  = tid >> 2;
    const int gsub = tid & 3;

    for (int ii = tid; ii < FEAT; ii += 256) xs[ii + 1] = x[(size_t)b*FEAT + ii];
    for (int ii = tid; ii < HID*3; ii += 256) w1s[ii] = w1[ii];
    if (tid < HID) b1s[tid] = b1[tid];
    if (tid == 0) { xs[0] = 0.f; xs[FEAT + 1] = 0.f; xs[FEAT + 2] = 0.f; }

    float bl[4];
    #pragma unroll
    for (int j = 0; j < 4; j++) bl[j] = b2[l0 + j];

    double zp[4] = {0.0, 0.0, 0.0, 0.0};
    __syncthreads();

    const int t0 = ch * TCX;

    ull acc[2][16];
    #pragma unroll
    for (int p = 0; p < 2; p++)
        #pragma unroll
        for (int ii = 0; ii < 16; ii++) acc[p][ii] = 0ull;

    for (int g = 0; g < 4; g++) {
        __syncthreads();
        {
            const int c  = g*CG + gcc;
            const float wa = w1s[c*3+0], wb = w1s[c*3+1], wc = w1s[c*3+2];
            const float bb1 = b1s[c];
            #pragma unroll
            for (int s = 0; s < 33; s++) {
                int tt = gsub + 4*s;
                if (tt < TCX + 2) {
                    int t = t0 - 1 + tt;
                    float v = 0.f;
                    if ((unsigned)t < (unsigned)FEAT) {
                        v = __fmul_rn(wa, xs[t]);
                        v = __fmaf_rn(wb, xs[t+1], v);
                        v = __fmaf_rn(wc, xs[t+2], v);
                        v = fmaxf(__fadd_rn(v, bb1), 0.f);
                    }
                    r1s2[gcc*RSP + tt] = splat2(v);
                }
            }
        }

        #pragma unroll
        for (int k = 0; k < 3; k++) {
            __syncthreads();
            {
                const float4* src = (const float4*)(g_w2t + (size_t)(k*HID + g*CG)*LAT);
                float4* dst = (float4*)(sm + EW2T_O);
                #pragma unroll
                for (int r = 0; r < 8; r++) dst[tid + r*256] = src[tid + r*256];
            }
            __syncthreads();

            #pragma unroll 2
            for (int kk = 0; kk < CG; kk++) {
                ulonglong2 a2 = wt[kk*32 + lane];
                const ulonglong2* brow =
                    (const ulonglong2*)(r1s2 + kk*RSP) + w8*8;
                #pragma unroll
                for (int j = 0; j < 9; j++) {
                    ulonglong2 bb = brow[j];
                    const int i0 = 2*j - k;
                    const int i1 = 2*j + 1 - k;
                    if (i0 >= 0 && i0 < 16) {
                        acc[0][i0] = ffma2(a2.x, bb.x, acc[0][i0]);
                        acc[1][i0] = ffma2(a2.y, bb.x, acc[1][i0]);
                    }
                    if (i1 >= 0 && i1 < 16) {
                        acc[0][i1] = ffma2(a2.x, bb.y, acc[0][i1]);
                        acc[1][i1] = ffma2(a2.y, bb.y, acc[1][i1]);
                    }
                }
            }
        }
    }

    #pragma unroll
    for (int ii = 0; ii < 16; ii++) {
        if (t0 + w8*16 + ii < FEAT) {
            #pragma unroll
            for (int p = 0; p < 2; p++) {
                float2 f = unpack2(acc[p][ii]);
                zp[2*p+0] += (double)fmaxf(__fadd_rn(f.x, bl[2*p+0]), 0.f);
                zp[2*p+1] += (double)fmaxf(__fadd_rn(f.y, bl[2*p+1]), 0.f);
            }
        }
    }

    __syncthreads();
    double* dp = (double*)(sm + ER1_O);
    #pragma unroll
    for (int j = 0; j < 4; j++) dp[w8*128 + l0 + j] = zp[j];
    __syncthreads();
    if (tid < LAT) {
        double v = dp[tid];
        #pragma unroll
        for (int w = 1; w < 8; w++) v += dp[w*128 + tid];
        g_zpart[(size_t)(b*NT + ch)*LAT + tid] = v;
    }
}

// --------------------- fixed rows: reduce + RVQ redo ------------------------
__global__ void fix_reduce()
{
    int idx = blockIdx.x * blockDim.x + threadIdx.x;
    int p = idx >> 7;
    if (p >= g_flagcnt) return;
    int b = g_flaglist[p];
    int l = idx & 127;
    double s = 0.0;
    #pragma unroll
    for (int t = 0; t < NT; t++)
        s += g_zpart[(size_t)(b*NT + t)*LAT + l];
    g_z[(size_t)b*LAT + l] = __fdiv_rn((float)s, (float)FEAT);
}

__global__ void __launch_bounds__(256)
rvq_fix(const float* __restrict__ cb,
        float* __restrict__ out_zq, float* __restrict__ out_idx,
        int write_zq, int write_idx)
{
    __shared__ __align__(16) float res[8][LAT];
    __shared__ int sidx[8][NQ];

    const int tid  = threadIdx.x;
    const int w    = tid >> 5;
    const int lane = tid & 31;
    const int slot = blockIdx.x * 8 + w;
    if (slot >= g_flagcnt) return;
    const int b = g_flaglist[slot];

    float qs[4] = {0.f, 0.f, 0.f, 0.f};
    #pragma unroll
    for (int m = 0; m < 4; m++)
        res[w][lane + 32*m] = g_z[(size_t)b*LAT + lane + 32*m];
    __syncwarp();

    rvq_row(cb, res[w], qs, sidx[w], lane, 0, b);

    if (write_zq) {
        #pragma unroll
        for (int m = 0; m < 4; m++)
            out_zq[(size_t)b*LAT + lane + 32*m] = qs[m];
    }
    if (write_idx && lane < NQ)
        out_idx[(size_t)b*NQ + lane] = (float)sidx[w][lane];
}

// ---------------------------------------------------------------------------
extern "C" void kernel_launch(void* const* d_in, const int* in_sizes, int n_in,
                              void* d_out, int out_size)
{
    const float* x  = (const float*)d_in[0];
    const float* w1 = (const float*)d_in[1];
    const float* b1 = (const float*)d_in[2];
    const float* w2 = (const float*)d_in[3];
    const float* b2 = (const float*)d_in[4];
    const float* cb = (const float*)d_in[5];

    cudaFuncSetAttribute(encoder_fast,
                         cudaFuncAttributeMaxDynamicSharedMemorySize,
                         FAST_SMEM_BYTES);
    cudaFuncSetAttribute(exact_chunk,
                         cudaFuncAttributeMaxDynamicSharedMemorySize,
                         EX_SMEM_BYTES);

    float* out_zq  = (float*)d_out;
    float* out_idx = (float*)d_out + (size_t)B_SZ*LAT;
    int write_zq = 1, write_idx = 1;
    if (out_size >= B_SZ*(LAT + NQ)) {
    } else if (out_size >= B_SZ*LAT) {
        write_idx = 0;
    } else {
        write_zq = 0;
        out_idx  = (float*)d_out;
    }

    const int total = NBFRAG + KTOT*LAT + NQ*NEMB;
    prep_kernel<<<(total + 255)/256, 256>>>(w2, cb);
    encoder_fast<<<TILES_TOT, 256, FAST_SMEM_BYTES>>>(x, w1, b1, b2);
    reduce_kernel<<<(B_SZ*LAT + 255)/256, 256>>>();
    rvq_flag<<<B_SZ/8, 256>>>(cb, out_zq, out_idx, write_zq, write_idx);
    exact_chunk<<<TILES_TOT, 256, EX_SMEM_BYTES>>>(x, w1, b1, b2);
    fix_reduce<<<(B_SZ*LAT + 255)/256, 256>>>();
    rvq_fix<<<B_SZ/8, 256>>>(cb, out_zq, out_idx, write_zq, write_idx);
}